// round 5
// baseline (speedup 1.0000x reference)
#include <cuda_runtime.h>
#include <math.h>

#define NS 4
#define TPB 128
// per-h table layout (floats):
// [0,28)    Pr[k*4+n]      A_bar^(4<<k) real, k=0..6
// [28,56)   Pi[k*4+n]      imag
// [56,84)   Pin[k*4+n]     -imag
// [84,88)   Sr[n]          A_bar^512 real
// [88,92)   Si[n]          imag
// [92,96)   Sin[n]         -imag
// [96,100)  p[n]           2*Re(S)
// [100,104) q[n]           -|S|^2
// [104,116) cc[(i-1)*4+n]  Re(A_bar^i), i=1..3
// [116,128) cs[(i-1)*4+n]  -Im(A_bar^i)
// [128,132) Kr[n]          coef real
// [132,136) Ki[n]          coef imag
#define TABF 136

__device__ float g_tab[2048 * TABF];

typedef unsigned long long ull;

__device__ __forceinline__ ull pk2(float lo, float hi) {
    ull r; asm("mov.b64 %0, {%1,%2};" : "=l"(r) : "f"(lo), "f"(hi)); return r;
}
__device__ __forceinline__ float2 unpk2(ull v) {
    float2 f; asm("mov.b64 {%0,%1}, %2;" : "=f"(f.x), "=f"(f.y) : "l"(v)); return f;
}
__device__ __forceinline__ ull mul2(ull a, ull b) {
    ull r; asm("mul.rn.f32x2 %0, %1, %2;" : "=l"(r) : "l"(a), "l"(b)); return r;
}
__device__ __forceinline__ ull fma2(ull a, ull b, ull c) {
    ull r; asm("fma.rn.f32x2 %0, %1, %2, %3;" : "=l"(r) : "l"(a), "l"(b), "l"(c)); return r;
}
__device__ __forceinline__ ull add2(ull a, ull b) {
    ull r; asm("add.rn.f32x2 %0, %1, %2;" : "=l"(r) : "l"(a), "l"(b)); return r;
}

// ---------------- prep kernel: all transcendentals, fully parallel ----------------
__global__ void pmsn_prep(
    const float* __restrict__ log_dt,
    const float* __restrict__ log_A_real,
    const float* __restrict__ A_imag,
    const float* __restrict__ VinvB_real,
    const float* __restrict__ VinvB_imag,
    const float* __restrict__ CV_real,
    const float* __restrict__ CV_imag,
    int H)
{
    const int tid = blockIdx.x * blockDim.x + threadIdx.x;
    if (tid >= H * 48) return;
    const int h = tid / 48;
    const int r = tid % 48;
    const int n = r / 12;
    const int j = r % 12;
    if (j == 11) return;

    const int idx = h * NS + n;
    const float dt  = expf(log_dt[h]);
    const float Are = -expf(log_A_real[idx]);
    const float Aim = A_imag[idx];
    const float adr = Are * dt;
    const float adi = Aim * dt;

    const int e = (j < 7) ? (4 << j) : (j == 7 ? 512 : (j - 7));

    const double TWO_PI     = 6.283185307179586476925286766559;
    const double INV_TWO_PI = 0.15915494309189533576888376337251;
    double ph = (double)adi * (double)e;
    ph -= floor(ph * INV_TWO_PI) * TWO_PI;
    float s, c;
    sincosf((float)ph, &s, &c);
    const float m  = expf(adr * (float)e);
    const float re = m * c, im = m * s;

    float* T = g_tab + h * TABF;
    if (j < 7) {
        T[j * 4 + n]      = re;
        T[28 + j * 4 + n] = im;
        T[56 + j * 4 + n] = -im;
    } else if (j == 7) {
        T[84 + n] = re;
        T[88 + n] = im;
        T[92 + n] = -im;
        T[96 + n]  = re + re;
        T[100 + n] = -(re * re + im * im);
    } else {
        const int i = j - 8;
        T[104 + i * 4 + n] = re;
        T[116 + i * 4 + n] = -im;
        if (i == 0) {
            // this lane holds A_bar = exp(Adt); coef = C * (A_bar-1)/A * B
            const float inv = 1.0f / (Are * Are + Aim * Aim);
            const float iAr =  Are * inv, iAi = -Aim * inv;
            const float mr = re - 1.0f, mi = im;
            const float qr = mr * iAr - mi * iAi;
            const float qi = mr * iAi + mi * iAr;
            const float Br = VinvB_real[idx], Bi = VinvB_imag[idx];
            const float bbr = qr * Br - qi * Bi;
            const float bbi = qr * Bi + qi * Br;
            const float Cr = CV_real[idx], Ci = CV_imag[idx];
            T[128 + n] = Cr * bbr - Ci * bbi;
            T[132 + n] = Cr * bbi + Ci * bbr;
        }
    }
}

// ---------------- main kernel: pure FMA + stores ----------------
__global__ __launch_bounds__(TPB) void pmsn_main(float* __restrict__ out, int L)
{
    __shared__ __align__(16) float tb[TABF];
    const int h = blockIdx.x;
    const int t = threadIdx.x;

    if (t < TABF / 4)
        ((float4*)tb)[t] = ((const float4*)(g_tab + (size_t)h * TABF))[t];
    __syncthreads();

    // start state: v = coef * A_bar^(4t), n-pair packed bit product
    ull vr[2], vi[2];
    vr[0] = *(const ull*)&tb[128]; vr[1] = *(const ull*)&tb[130];
    vi[0] = *(const ull*)&tb[132]; vi[1] = *(const ull*)&tb[134];
#pragma unroll
    for (int k = 0; k < 7; ++k) {
        if ((t >> k) & 1) {
#pragma unroll
            for (int p = 0; p < 2; ++p) {
                const ull br = *(const ull*)&tb[k * 4 + 2 * p];
                const ull bi = *(const ull*)&tb[28 + k * 4 + 2 * p];
                const ull bn = *(const ull*)&tb[56 + k * 4 + 2 * p];
                const ull nr = fma2(vi[p], bn, mul2(vr[p], br)); // vr*br - vi*bi
                const ull ni = fma2(vi[p], br, mul2(vr[p], bi)); // vr*bi + vi*br
                vr[p] = nr; vi[p] = ni;
            }
        }
    }

    // u = v * S (second history point)
    ull ur[2], ui[2];
#pragma unroll
    for (int p = 0; p < 2; ++p) {
        const ull br = *(const ull*)&tb[84 + 2 * p];
        const ull bi = *(const ull*)&tb[88 + 2 * p];
        const ull bn = *(const ull*)&tb[92 + 2 * p];
        ur[p] = fma2(vi[p], bn, mul2(vr[p], br));
        ui[p] = fma2(vi[p], br, mul2(vr[p], bi));
    }

    // unpack to scalars, build phase-packed states
    float vre[NS], vim[NS], ure[NS], uim[NS];
#pragma unroll
    for (int p = 0; p < 2; ++p) {
        float2 a;
        a = unpk2(vr[p]); vre[2*p] = a.x; vre[2*p+1] = a.y;
        a = unpk2(vi[p]); vim[2*p] = a.x; vim[2*p+1] = a.y;
        a = unpk2(ur[p]); ure[2*p] = a.x; ure[2*p+1] = a.y;
        a = unpk2(ui[p]); uim[2*p] = a.x; uim[2*p+1] = a.y;
    }

    ull xp01[NS], xp23[NS], xc01[NS], xc23[NS], p2[NS], q2[NS];
#pragma unroll
    for (int n = 0; n < NS; ++n) {
        const float c1 = tb[104 + n], s1 = tb[116 + n];   // s = -sin
        const float c2 = tb[108 + n], s2 = tb[120 + n];
        const float c3 = tb[112 + n], s3 = tb[124 + n];
        xp01[n] = pk2(vre[n],                         fmaf(vim[n], s1, vre[n] * c1));
        xp23[n] = pk2(fmaf(vim[n], s2, vre[n] * c2),  fmaf(vim[n], s3, vre[n] * c3));
        xc01[n] = pk2(ure[n],                         fmaf(uim[n], s1, ure[n] * c1));
        xc23[n] = pk2(fmaf(uim[n], s2, ure[n] * c2),  fmaf(uim[n], s3, ure[n] * c3));
        p2[n] = pk2(tb[96 + n],  tb[96 + n]);
        q2[n] = pk2(tb[100 + n], tb[100 + n]);
    }

    float* __restrict__ orow = out + (size_t)h * (size_t)L + 4 * t;
    const int NJ = L >> 9;    // L / 512

    // j = 0, 1 from history
    {
        const ull a01 = add2(add2(xp01[0], xp01[1]), add2(xp01[2], xp01[3]));
        const ull a23 = add2(add2(xp23[0], xp23[1]), add2(xp23[2], xp23[3]));
        const float2 a = unpk2(a01), b = unpk2(a23);
        *(float4*)orow = make_float4(a.x, a.y, b.x, b.y);
    }
    if (NJ > 1) {
        const ull a01 = add2(add2(xc01[0], xc01[1]), add2(xc01[2], xc01[3]));
        const ull a23 = add2(add2(xc23[0], xc23[1]), add2(xc23[2], xc23[3]));
        const float2 a = unpk2(a01), b = unpk2(a23);
        *(float4*)(orow + 512) = make_float4(a.x, a.y, b.x, b.y);
    }

    // Chebyshev recurrence: x_j = p*x_{j-1} + q*x_{j-2}
#pragma unroll 6
    for (int j = 2; j < NJ; ++j) {
#pragma unroll
        for (int n = 0; n < NS; ++n) {
            const ull t01 = fma2(p2[n], xc01[n], mul2(q2[n], xp01[n]));
            xp01[n] = xc01[n]; xc01[n] = t01;
            const ull t23 = fma2(p2[n], xc23[n], mul2(q2[n], xp23[n]));
            xp23[n] = xc23[n]; xc23[n] = t23;
        }
        const ull a01 = add2(add2(xc01[0], xc01[1]), add2(xc01[2], xc01[3]));
        const ull a23 = add2(add2(xc23[0], xc23[1]), add2(xc23[2], xc23[3]));
        const float2 a = unpk2(a01), b = unpk2(a23);
        *(float4*)(orow + (size_t)j * 512) = make_float4(a.x, a.y, b.x, b.y);
    }
}

extern "C" void kernel_launch(void* const* d_in, const int* in_sizes, int n_in,
                              void* d_out, int out_size) {
    const float* log_dt     = (const float*)d_in[0];
    const float* log_A_real = (const float*)d_in[1];
    const float* A_imag     = (const float*)d_in[2];
    const float* VinvB_real = (const float*)d_in[3];
    const float* VinvB_imag = (const float*)d_in[4];
    const float* CV_real    = (const float*)d_in[5];
    const float* CV_imag    = (const float*)d_in[6];
    const int H = in_sizes[0];               // 2048
    const int L = out_size / H;              // 4096

    const int prep_threads = H * 48;
    pmsn_prep<<<(prep_threads + 255) / 256, 256>>>(
        log_dt, log_A_real, A_imag, VinvB_real, VinvB_imag, CV_real, CV_imag, H);
    pmsn_main<<<H, TPB>>>((float*)d_out, L);
}

// round 6
// speedup vs baseline: 1.2937x; 1.2937x over previous
#include <cuda_runtime.h>
#include <math.h>

#define NS 4
#define TPB 128
#define NEXP 39   // exponent table entries per n

__device__ __forceinline__ float2 cmul(float2 a, float2 b) {
    float2 r;
    r.x = fmaf(-a.y, b.y, a.x * b.x);
    r.y = fmaf( a.x, b.y, a.y * b.x);
    return r;
}

// exponent for table index i
__device__ __forceinline__ int exp_of(int i) {
    if (i < 31) return 4 * (i + 1);     // 4..124   (P4[r], r=1..31 -> i=r-1)
    if (i < 34) return i - 30;          // 1,2,3    (rotators / A_bar)
    if (i < 38) return 128 * (i - 34);  // 0,128,256,384 (W[q], q=i-34; e=0 -> identity)
    return 512;                         // S
}

__global__ __launch_bounds__(TPB) void pmsn_kernel(
    const float* __restrict__ log_dt,
    const float* __restrict__ log_A_real,
    const float* __restrict__ A_imag,
    const float* __restrict__ VinvB_real,
    const float* __restrict__ VinvB_imag,
    const float* __restrict__ CV_real,
    const float* __restrict__ CV_imag,
    float* __restrict__ out, int L)
{
    const int h = blockIdx.x;
    const int t = threadIdx.x;

    __shared__ float2 Etab[NEXP][NS];  // A_bar^e (re, im)
    __shared__ float2 Rot[3][NS];      // (cos, -sin) of A_bar^i, i=1..3
    __shared__ float2 PQ[NS];          // (p, q) = (2 Re S, -|S|^2)
    __shared__ float2 Coef[NS];        // C * B_bar

    // ---- phase A: transcendental bundles (156 jobs over 128 lanes) ----
    const double TWO_PI     = 6.283185307179586476925286766559;
    const double INV_TWO_PI = 0.15915494309189533576888376337251;
#pragma unroll
    for (int pass = 0; pass < 2; ++pass) {
        const int job = t + pass * TPB;
        if (job < NEXP * NS) {
            const int n = job & 3;
            const int i = job >> 2;
            const int e = exp_of(i);
            const int idx = h * NS + n;
            const float dt  = expf(log_dt[h]);
            const float Are = -expf(log_A_real[idx]);
            const float adr = Are * dt;
            const float adi = A_imag[idx] * dt;
            double ph = (double)adi * (double)e;
            ph -= floor(ph * INV_TWO_PI) * TWO_PI;
            float s, c;
            sincosf((float)ph, &s, &c);
            const float m = expf(adr * (float)e);
            Etab[i][n] = make_float2(m * c, m * s);
        }
    }
    __syncthreads();

    // ---- phase B: combine (4 lanes) ----
    if (t < NS) {
        const int n = t;
        const int idx = h * NS + n;
        // rotators with negated sin
        const float2 a1 = Etab[31][n];
        Rot[0][n] = make_float2(a1.x, -a1.y);
        const float2 a2 = Etab[32][n];
        Rot[1][n] = make_float2(a2.x, -a2.y);
        const float2 a3 = Etab[33][n];
        Rot[2][n] = make_float2(a3.x, -a3.y);
        // p, q from S
        const float2 S = Etab[38][n];
        PQ[n] = make_float2(S.x + S.x, -fmaf(S.x, S.x, S.y * S.y));
        // coef = C * (A_bar - 1)/A * B
        const float dt  = expf(log_dt[h]);
        const float Are = -expf(log_A_real[idx]);
        const float Aim = A_imag[idx];
        (void)dt;
        const float inv = 1.0f / fmaf(Are, Are, Aim * Aim);
        const float iAr =  Are * inv, iAi = -Aim * inv;
        const float mr = a1.x - 1.0f, mi = a1.y;
        const float qr = mr * iAr - mi * iAi;
        const float qi = mr * iAi + mi * iAr;
        const float Br = VinvB_real[idx], Bi = VinvB_imag[idx];
        const float bbr = qr * Br - qi * Bi;
        const float bbi = qr * Bi + qi * Br;
        const float Cr = CV_real[idx], Ci = CV_imag[idx];
        Coef[n] = make_float2(Cr * bbr - Ci * bbi, Cr * bbi + Ci * bbr);
    }
    __syncthreads();

    // ---- per-thread start states ----
    // thread t covers l = 4t + ph + 512j ; t = 32q + r
    const int q = t >> 5;
    const int r = t & 31;
    const int eW = 34 + q;              // A_bar^(128q)  (q=0 -> e=0 identity)
    const int eR = r ? (r - 1) : 34;    // A_bar^(4r)    (r=0 -> identity)

    float xc[NS][4], xp[NS][4], pn[NS], qn[NS];
#pragma unroll
    for (int n = 0; n < NS; ++n) {
        float2 v = cmul(Etab[eW][n], Etab[eR][n]);   // A_bar^(4t)
        v = cmul(v, Coef[n]);                        // * coef
        const float2 u = cmul(v, Etab[38][n]);       // * S (second history)
        xp[n][0] = v.x;
        xc[n][0] = u.x;
#pragma unroll
        for (int i = 0; i < 3; ++i) {
            const float2 ro = Rot[i][n];             // (c, -s)
            xp[n][i + 1] = fmaf(v.y, ro.y, v.x * ro.x);
            xc[n][i + 1] = fmaf(u.y, ro.y, u.x * ro.x);
        }
        const float2 pq = PQ[n];
        pn[n] = pq.x;
        qn[n] = pq.y;
    }

    float* __restrict__ orow = out + (size_t)h * (size_t)L + 4 * t;
    const int NJ = L >> 9;    // L / 512

    // j = 0, 1 from history
    *(float4*)orow = make_float4(
        (xp[0][0] + xp[1][0]) + (xp[2][0] + xp[3][0]),
        (xp[0][1] + xp[1][1]) + (xp[2][1] + xp[3][1]),
        (xp[0][2] + xp[1][2]) + (xp[2][2] + xp[3][2]),
        (xp[0][3] + xp[1][3]) + (xp[2][3] + xp[3][3]));
    if (NJ > 1)
        *(float4*)(orow + 512) = make_float4(
            (xc[0][0] + xc[1][0]) + (xc[2][0] + xc[3][0]),
            (xc[0][1] + xc[1][1]) + (xc[2][1] + xc[3][1]),
            (xc[0][2] + xc[1][2]) + (xc[2][2] + xc[3][2]),
            (xc[0][3] + xc[1][3]) + (xc[2][3] + xc[3][3]));

    // Chebyshev: x_j = p*x_{j-1} + q*x_{j-2}
#pragma unroll 6
    for (int j = 2; j < NJ; ++j) {
        float s0, s1, s2, s3;
#pragma unroll
        for (int n = 0; n < NS; ++n) {
#pragma unroll
            for (int i = 0; i < 4; ++i) {
                const float xn = fmaf(pn[n], xc[n][i], qn[n] * xp[n][i]);
                xp[n][i] = xc[n][i];
                xc[n][i] = xn;
            }
        }
        s0 = (xc[0][0] + xc[1][0]) + (xc[2][0] + xc[3][0]);
        s1 = (xc[0][1] + xc[1][1]) + (xc[2][1] + xc[3][1]);
        s2 = (xc[0][2] + xc[1][2]) + (xc[2][2] + xc[3][2]);
        s3 = (xc[0][3] + xc[1][3]) + (xc[2][3] + xc[3][3]);
        *(float4*)(orow + (size_t)j * 512) = make_float4(s0, s1, s2, s3);
    }
}

extern "C" void kernel_launch(void* const* d_in, const int* in_sizes, int n_in,
                              void* d_out, int out_size) {
    const float* log_dt     = (const float*)d_in[0];
    const float* log_A_real = (const float*)d_in[1];
    const float* A_imag     = (const float*)d_in[2];
    const float* VinvB_real = (const float*)d_in[3];
    const float* VinvB_imag = (const float*)d_in[4];
    const float* CV_real    = (const float*)d_in[5];
    const float* CV_imag    = (const float*)d_in[6];
    const int H = in_sizes[0];               // 2048
    const int L = out_size / H;              // 4096
    pmsn_kernel<<<H, TPB>>>(log_dt, log_A_real, A_imag,
                            VinvB_real, VinvB_imag,
                            CV_real, CV_imag, (float*)d_out, L);
}